// round 11
// baseline (speedup 1.0000x reference)
#include <cuda_runtime.h>
#include <cuda_fp16.h>
#include <cstdint>

#define HH 256
#define WW 256
#define NB 8
#define PLANE (HH*WW)
#define CIN 256
#define CHID 16

// per-sample demodulated conv weights, fp16 half2-packed, dense:
// [b][tap][o][32 words]  (word ip = channels 2ip, 2ip+1)
__device__ unsigned g_wmodh[NB * 9 * 64 * 32];

// ---------------------------------------------------------------------------
// Kernel 1: fused style MLP + modulation + demodulation.
// One block per (o, b); MLP recomputed redundantly per block (tiny, L2-hot).
// ---------------------------------------------------------------------------
__global__ __launch_bounds__(64)
void style_kernel(const float* __restrict__ vec,
                  const float* __restrict__ w1,
                  const float* __restrict__ w2,
                  const float* __restrict__ wconv) {
    const int o = blockIdx.x, b = blockIdx.y, tid = threadIdx.x;
    __shared__ float sv[CIN], sh[CHID], ssty[64];
    __shared__ float red[2];
    __shared__ float sd;

    #pragma unroll
    for (int i = 0; i < 4; ++i) sv[tid + 64*i] = vec[b*CIN + tid + 64*i];
    __syncthreads();

    // w1 GEMV: thread t -> (h = t>>2, quarter q = t&3)
    {
        const int h = tid >> 2, q = tid & 3;
        const float* wrow = w1 + h*CIN + q*64;
        const float* svq  = sv + q*64;
        float a = 0.f;
        #pragma unroll 16
        for (int c = 0; c < 64; ++c) a += svq[c] * wrow[c];
        a += __shfl_xor_sync(0xffffffffu, a, 1);
        a += __shfl_xor_sync(0xffffffffu, a, 2);
        if ((tid & 3) == 0) sh[h] = (a > 0.f) ? a : 0.1f * a;  // LeakyReLU(0.1)
    }
    __syncthreads();

    // w2 GEMV: thread = out channel
    {
        float a = 0.f;
        #pragma unroll
        for (int j = 0; j < CHID; ++j) a += sh[j] * w2[tid*CHID + j];
        ssty[tid] = a + 1.0f;                          // sty + 1
    }
    __syncthreads();

    // modulate + demodulate this block's output channel o
    const float* wo = wconv + o * 576;
    float acc = 0.f;
    #pragma unroll
    for (int k = 0; k < 9; ++k) {
        const int idx = k*64 + tid;                    // idx = i*9 + t
        const float v = wo[idx] * ssty[idx / 9];
        acc += v * v;
    }
    #pragma unroll
    for (int s = 16; s; s >>= 1) acc += __shfl_xor_sync(0xffffffffu, acc, s);
    if ((tid & 31) == 0) red[tid >> 5] = acc;
    __syncthreads();
    if (tid == 0) sd = rsqrtf(red[0] + red[1] + 1e-8f);
    __syncthreads();
    const float d = sd;

    for (int m = tid; m < 288; m += 64) {
        const int ip = m / 9, t = m % 9;
        const int i0 = 2 * ip;
        const float v0 = wo[i0*9 + t]     * ssty[i0]   * d;
        const float v1 = wo[(i0+1)*9 + t] * ssty[i0+1] * d;
        __half2 h = __floats2half2_rn(v0, v1);
        g_wmodh[(size_t)((b*9 + t)*64 + o)*32 + ip] = *(unsigned*)&h;
    }
}

// ---------------------------------------------------------------------------
// Kernel 2: fused ChanNorm + modulated 3x3 conv (fp16 m16n8k16, ldmatrix) + res
// CTA tile: 8 rows x 32 cols x 64 out-ch.  8 warps, warp = one output row.
// xs: [pix = r*34+cc][36 words]; wt: double-buffered [2][64][36 words].
// Row stride 36 words = 9 chunks (== 1 mod 8): ldmatrix 8-row fetches AND
// uint4 STS phases are both conflict-free without swizzling.
// SMEM_WORDS covers the epilogue staging region too: 8 warps * 2304 words.
// ---------------------------------------------------------------------------
#define XW 36
#define NPX 340                          /* 10 halo rows * 34 halo cols */
#define OFF_WT (NPX*XW)                  /* 12240 words */
#define WTBUF  (64*XW)                   /* 2304 words per buffer */
#define OFF_G  (OFF_WT + 2*WTBUF)
#define OFF_B  (OFF_G + 64)
#define SMEM_WORDS 18448                 /* >= max(OFF_B+64, 8*2304) */

__device__ __forceinline__ uint32_t smem_u32(const void* p) {
    uint32_t a;
    asm("{ .reg .u64 t; cvta.to.shared.u64 t, %1; cvt.u32.u64 %0, t; }" : "=r"(a) : "l"(p));
    return a;
}
__device__ __forceinline__ void ldsm_x4(unsigned r[4], uint32_t addr) {
    asm volatile("ldmatrix.sync.aligned.m8n8.x4.shared.b16 {%0,%1,%2,%3}, [%4];"
        : "=r"(r[0]), "=r"(r[1]), "=r"(r[2]), "=r"(r[3]) : "r"(addr));
}
__device__ __forceinline__ void mma_f16(float c[4],
                                        unsigned a0, unsigned a1,
                                        unsigned a2, unsigned a3,
                                        unsigned b0, unsigned b1) {
    asm volatile(
        "mma.sync.aligned.m16n8k16.row.col.f32.f16.f16.f32 "
        "{%0,%1,%2,%3}, {%4,%5,%6,%7}, {%8,%9}, {%0,%1,%2,%3};\n"
        : "+f"(c[0]), "+f"(c[1]), "+f"(c[2]), "+f"(c[3])
        : "r"(a0), "r"(a1), "r"(a2), "r"(a3), "r"(b0), "r"(b1));
}

__global__ __launch_bounds__(256, 2)
void conv_kernel(const float* __restrict__ x,
                 const float* __restrict__ gaff,
                 const float* __restrict__ baff,
                 float* __restrict__ out) {
    extern __shared__ unsigned sm[];
    unsigned* xs = sm;
    float* sg = (float*)(sm + OFF_G);
    float* sb = (float*)(sm + OFF_B);

    const int tid = threadIdx.x, warp = tid >> 5, lane = tid & 31;
    const int gq = lane >> 2, tq = lane & 3;
    const int x0 = blockIdx.x * 32, y0 = blockIdx.y * 8, b = blockIdx.z;
    const float* xb = x + (size_t)b * 64 * PLANE;

    if (tid < 64) { sg[tid] = gaff[tid]; sb[tid] = baff[tid]; }
    __syncthreads();

    // ---- ChanNorm halo tile -> fp16 half2 smem (uint4 conflict-free STS) ----
    for (int p = tid; p < NPX; p += 256) {
        const int r = p / 34, cc = p % 34;
        const int gy = y0 - 1 + r, gx = x0 - 1 + cc;
        uint4* dst = (uint4*)(xs + p * XW);
        if (gy >= 0 && gy < HH && gx >= 0 && gx < WW) {
            const float* px = xb + (size_t)gy * WW + gx;
            float v[64], s = 0.f, s2 = 0.f;
            #pragma unroll
            for (int c = 0; c < 64; ++c) v[c] = px[(size_t)c * PLANE];
            #pragma unroll
            for (int c = 0; c < 64; ++c) { s += v[c]; s2 += v[c]*v[c]; }
            const float mean = s * (1.f/64.f);
            const float rstd = rsqrtf(s2 * (1.f/64.f) - mean*mean + 1e-5f);
            #pragma unroll
            for (int u = 0; u < 8; ++u) {
                uint4 w;
                unsigned* wp = (unsigned*)&w;
                #pragma unroll
                for (int q = 0; q < 4; ++q) {
                    const int c0 = u*8 + q*2;
                    float n0 = (v[c0]   - mean) * rstd * sg[c0]   + sb[c0];
                    float n1 = (v[c0+1] - mean) * rstd * sg[c0+1] + sb[c0+1];
                    __half2 h = __floats2half2_rn(n0, n1);
                    wp[q] = *(unsigned*)&h;
                }
                dst[u] = w;
            }
        } else {
            const uint4 z = {0u,0u,0u,0u};
            #pragma unroll
            for (int u = 0; u < 8; ++u) dst[u] = z;     // pad AFTER norm
        }
    }

    // ---- weight prefetch machinery (uint4, conflict-free) ----
    const unsigned* wbase = g_wmodh + (size_t)(b * 9) * 2048;
    const int wdo = (tid >> 2) * XW + (tid & 3) * 8;   // dst word offset
    uint4 wr[2];
    {   // tap 0 -> regs -> wt buffer 0 ; tap 1 -> regs
        const uint4* s4 = (const uint4*)wbase + tid * 2;
        wr[0] = s4[0]; wr[1] = s4[1];
        uint4* d = (uint4*)(sm + OFF_WT + wdo);
        d[0] = wr[0]; d[1] = wr[1];
        const uint4* s4b = (const uint4*)(wbase + 2048) + tid * 2;
        wr[0] = s4b[0]; wr[1] = s4b[1];
    }

    // ---- ldmatrix base addresses (byte, shared space) ----
    const uint32_t xs_sa = smem_u32(sm);
    const uint32_t wt_sa = xs_sa + OFF_WT * 4;
    const uint32_t A0 = xs_sa + ((warp * 34 + (lane & 15)) * XW) * 4 + (lane >> 4) * 16;
    const uint32_t B0 = wt_sa + (((lane & 7) + ((lane >> 4) & 1) * 8) * XW) * 4
                              + ((lane >> 3) & 1) * 16;

    __syncthreads();                                   // xs + wt0 ready

    float acc[2][8][4];
    #pragma unroll
    for (int mt = 0; mt < 2; ++mt)
        #pragma unroll
        for (int nt = 0; nt < 8; ++nt)
            #pragma unroll
            for (int j = 0; j < 4; ++j) acc[mt][nt][j] = 0.f;

    for (int j = 0; j < 9; ++j) {
        const int ky = j / 3, kx = j % 3, s = j & 1;
        const uint32_t Abase = A0 + (uint32_t)((ky * 34 + kx) * XW) * 4;
        const uint32_t Bbase = B0 + (uint32_t)(s * WTBUF) * 4;

        #pragma unroll
        for (int kt = 0; kt < 4; ++kt) {
            const uint32_t ko = (uint32_t)kt * 32;
            unsigned a[2][4], bq[4][4];
            ldsm_x4(a[0], Abase + ko);
            ldsm_x4(a[1], Abase + ko + 16 * XW * 4);
            #pragma unroll
            for (int q = 0; q < 4; ++q)
                ldsm_x4(bq[q], Bbase + ko + (uint32_t)(q * 16 * XW) * 4);
            #pragma unroll
            for (int mt = 0; mt < 2; ++mt) {
                #pragma unroll
                for (int q = 0; q < 4; ++q) {
                    mma_f16(acc[mt][2*q],   a[mt][0], a[mt][1], a[mt][2], a[mt][3],
                            bq[q][0], bq[q][1]);
                    mma_f16(acc[mt][2*q+1], a[mt][0], a[mt][1], a[mt][2], a[mt][3],
                            bq[q][2], bq[q][3]);
                }
            }
        }

        if (j < 8) {
            uint4* d = (uint4*)(sm + OFF_WT + (s ^ 1) * WTBUF + wdo);
            d[0] = wr[0]; d[1] = wr[1];
            if (j < 7) {
                const uint4* s4 = (const uint4*)(wbase + (size_t)(j+2)*2048) + tid*2;
                wr[0] = s4[0]; wr[1] = s4[1];
            }
        }
        __syncthreads();
    }

    // ---- epilogue: stage acc -> smem [ch][36] (conflict-free), coalesced I/O ----
    __syncthreads();                          // all LDSM reads of xs/wt done
    float* ss = (float*)sm + warp * 2304;     // 64 ch x 36 floats per warp
    const int gy = y0 + warp;
    float* ob = out + (size_t)b * 64 * PLANE;

    #pragma unroll
    for (int mt = 0; mt < 2; ++mt) {
        const int px = mt*16 + gq;
        #pragma unroll
        for (int nt = 0; nt < 8; ++nt) {
            const int c0 = nt*8 + 2*tq;
            ss[c0*36 + px]         = acc[mt][nt][0];
            ss[(c0+1)*36 + px]     = acc[mt][nt][1];
            ss[c0*36 + px + 8]     = acc[mt][nt][2];
            ss[(c0+1)*36 + px + 8] = acc[mt][nt][3];
        }
    }
    __syncwarp();
    const size_t gbase = (size_t)gy * WW + x0 + lane;
    #pragma unroll 8
    for (int c = 0; c < 64; ++c) {
        const size_t gi = (size_t)c * PLANE + gbase;
        ob[gi] = xb[gi] + ss[c*36 + lane];
    }
}

// ---------------------------------------------------------------------------
extern "C" void kernel_launch(void* const* d_in, const int* in_sizes, int n_in,
                              void* d_out, int out_size) {
    (void)in_sizes; (void)n_in; (void)out_size;
    const float* x     = (const float*)d_in[0];
    const float* vec   = (const float*)d_in[1];
    const float* gaff  = (const float*)d_in[2];
    const float* baff  = (const float*)d_in[3];
    const float* w1    = (const float*)d_in[4];
    const float* w2    = (const float*)d_in[5];
    const float* wconv = (const float*)d_in[6];
    float* out = (float*)d_out;

    dim3 sgrid(64, NB);
    style_kernel<<<sgrid, 64>>>(vec, w1, w2, wconv);

    const int smem = SMEM_WORDS * 4;
    cudaFuncSetAttribute(conv_kernel,
                         cudaFuncAttributeMaxDynamicSharedMemorySize, smem);
    dim3 grid(WW/32, HH/8, NB);
    conv_kernel<<<grid, 256, smem>>>(x, gaff, baff, out);
}

// round 12
// speedup vs baseline: 1.0510x; 1.0510x over previous
#include <cuda_runtime.h>
#include <cuda_fp16.h>
#include <cstdint>

#define HH 256
#define WW 256
#define NB 8
#define PLANE (HH*WW)
#define CIN 256
#define CHID 16

// per-sample demodulated conv weights, fp16 half2-packed, dense:
// [b][tap][o][32 words]  (word ip = channels 2ip, 2ip+1)
__device__ unsigned g_wmodh[NB * 9 * 64 * 32];
// style vector (sty + 1), [b][64]
__device__ float g_sty[NB * 64];

// ---------------------------------------------------------------------------
// Kernel 1a: style MLP -> g_sty.  All 256 threads on the w1 GEMV:
// warp w handles hid = 2w + (lane>>4); 16 lanes x 16-elem chunks, shfl-reduce.
// ---------------------------------------------------------------------------
__global__ void mlp_kernel(const float* __restrict__ vec,
                           const float* __restrict__ w1,
                           const float* __restrict__ w2) {
    const int b = blockIdx.x, tid = threadIdx.x;
    const int warp = tid >> 5, lane = tid & 31;
    __shared__ float sv[CIN], sh[CHID];
    sv[tid] = vec[b*CIN + tid];
    __syncthreads();

    {
        const int h = 2*warp + (lane >> 4);
        const int c0 = (lane & 15) * 16;
        const float* wrow = w1 + h*CIN + c0;
        float acc = 0.f;
        #pragma unroll
        for (int i = 0; i < 16; ++i) acc += sv[c0 + i] * wrow[i];
        #pragma unroll
        for (int s = 8; s; s >>= 1)
            acc += __shfl_xor_sync(0xffffffffu, acc, s);
        if ((lane & 15) == 0)
            sh[h] = (acc > 0.f) ? acc : 0.1f * acc;    // LeakyReLU(0.1)
    }
    __syncthreads();
    if (tid < 64) {
        float acc = 0.f;
        #pragma unroll
        for (int j = 0; j < CHID; ++j) acc += sh[j] * w2[tid*CHID + j];
        g_sty[b*64 + tid] = acc + 1.0f;                // sty + 1
    }
}

// ---------------------------------------------------------------------------
// Kernel 1b: weight modulation + demodulation, one block per (o, b).
// ---------------------------------------------------------------------------
__global__ __launch_bounds__(64)
void demod_kernel(const float* __restrict__ wconv) {
    const int o = blockIdx.x, b = blockIdx.y, tid = threadIdx.x;
    __shared__ float ssty[64];
    __shared__ float red[2];
    __shared__ float sd;
    ssty[tid] = g_sty[b*64 + tid];
    __syncthreads();

    const float* wo = wconv + o * 576;
    float acc = 0.f;
    #pragma unroll
    for (int k = 0; k < 9; ++k) {
        const int idx = k*64 + tid;                    // idx = i*9 + t
        const float v = wo[idx] * ssty[idx / 9];
        acc += v * v;
    }
    #pragma unroll
    for (int s = 16; s; s >>= 1) acc += __shfl_xor_sync(0xffffffffu, acc, s);
    if ((tid & 31) == 0) red[tid >> 5] = acc;
    __syncthreads();
    if (tid == 0) sd = rsqrtf(red[0] + red[1] + 1e-8f);
    __syncthreads();
    const float d = sd;

    for (int m = tid; m < 288; m += 64) {
        const int ip = m / 9, t = m % 9;
        const int i0 = 2 * ip;
        const float v0 = wo[i0*9 + t]     * ssty[i0]   * d;
        const float v1 = wo[(i0+1)*9 + t] * ssty[i0+1] * d;
        __half2 h = __floats2half2_rn(v0, v1);
        g_wmodh[(size_t)((b*9 + t)*64 + o)*32 + ip] = *(unsigned*)&h;
    }
}

// ---------------------------------------------------------------------------
// Kernel 2: fused ChanNorm + modulated 3x3 conv (fp16 m16n8k16, ldmatrix) + res
// (exact R11 conv — best measured: 132.6us)
// CTA tile: 8 rows x 32 cols x 64 out-ch.  8 warps, warp = one output row.
// xs: [pix = r*34+cc][36 words]; wt: double-buffered [2][64][36 words].
// Row stride 36 words = 9 chunks (== 1 mod 8): ldmatrix 8-row fetches AND
// uint4 STS phases are both conflict-free without swizzling.
// ---------------------------------------------------------------------------
#define XW 36
#define NPX 340                          /* 10 halo rows * 34 halo cols */
#define OFF_WT (NPX*XW)                  /* 12240 words */
#define WTBUF  (64*XW)                   /* 2304 words per buffer */
#define OFF_G  (OFF_WT + 2*WTBUF)
#define OFF_B  (OFF_G + 64)
#define SMEM_WORDS 18448                 /* >= max(OFF_B+64, 8*2304) */

__device__ __forceinline__ uint32_t smem_u32(const void* p) {
    uint32_t a;
    asm("{ .reg .u64 t; cvta.to.shared.u64 t, %1; cvt.u32.u64 %0, t; }" : "=r"(a) : "l"(p));
    return a;
}
__device__ __forceinline__ void ldsm_x4(unsigned r[4], uint32_t addr) {
    asm volatile("ldmatrix.sync.aligned.m8n8.x4.shared.b16 {%0,%1,%2,%3}, [%4];"
        : "=r"(r[0]), "=r"(r[1]), "=r"(r[2]), "=r"(r[3]) : "r"(addr));
}
__device__ __forceinline__ void mma_f16(float c[4],
                                        unsigned a0, unsigned a1,
                                        unsigned a2, unsigned a3,
                                        unsigned b0, unsigned b1) {
    asm volatile(
        "mma.sync.aligned.m16n8k16.row.col.f32.f16.f16.f32 "
        "{%0,%1,%2,%3}, {%4,%5,%6,%7}, {%8,%9}, {%0,%1,%2,%3};\n"
        : "+f"(c[0]), "+f"(c[1]), "+f"(c[2]), "+f"(c[3])
        : "r"(a0), "r"(a1), "r"(a2), "r"(a3), "r"(b0), "r"(b1));
}

__global__ __launch_bounds__(256, 2)
void conv_kernel(const float* __restrict__ x,
                 const float* __restrict__ gaff,
                 const float* __restrict__ baff,
                 float* __restrict__ out) {
    extern __shared__ unsigned sm[];
    unsigned* xs = sm;
    float* sg = (float*)(sm + OFF_G);
    float* sb = (float*)(sm + OFF_B);

    const int tid = threadIdx.x, warp = tid >> 5, lane = tid & 31;
    const int gq = lane >> 2, tq = lane & 3;
    const int x0 = blockIdx.x * 32, y0 = blockIdx.y * 8, b = blockIdx.z;
    const float* xb = x + (size_t)b * 64 * PLANE;

    if (tid < 64) { sg[tid] = gaff[tid]; sb[tid] = baff[tid]; }
    __syncthreads();

    // ---- ChanNorm halo tile -> fp16 half2 smem (uint4 conflict-free STS) ----
    for (int p = tid; p < NPX; p += 256) {
        const int r = p / 34, cc = p % 34;
        const int gy = y0 - 1 + r, gx = x0 - 1 + cc;
        uint4* dst = (uint4*)(xs + p * XW);
        if (gy >= 0 && gy < HH && gx >= 0 && gx < WW) {
            const float* px = xb + (size_t)gy * WW + gx;
            float v[64], s = 0.f, s2 = 0.f;
            #pragma unroll
            for (int c = 0; c < 64; ++c) v[c] = px[(size_t)c * PLANE];
            #pragma unroll
            for (int c = 0; c < 64; ++c) { s += v[c]; s2 += v[c]*v[c]; }
            const float mean = s * (1.f/64.f);
            const float rstd = rsqrtf(s2 * (1.f/64.f) - mean*mean + 1e-5f);
            #pragma unroll
            for (int u = 0; u < 8; ++u) {
                uint4 w;
                unsigned* wp = (unsigned*)&w;
                #pragma unroll
                for (int q = 0; q < 4; ++q) {
                    const int c0 = u*8 + q*2;
                    float n0 = (v[c0]   - mean) * rstd * sg[c0]   + sb[c0];
                    float n1 = (v[c0+1] - mean) * rstd * sg[c0+1] + sb[c0+1];
                    __half2 h = __floats2half2_rn(n0, n1);
                    wp[q] = *(unsigned*)&h;
                }
                dst[u] = w;
            }
        } else {
            const uint4 z = {0u,0u,0u,0u};
            #pragma unroll
            for (int u = 0; u < 8; ++u) dst[u] = z;     // pad AFTER norm
        }
    }

    // ---- weight prefetch machinery (uint4, conflict-free) ----
    const unsigned* wbase = g_wmodh + (size_t)(b * 9) * 2048;
    const int wdo = (tid >> 2) * XW + (tid & 3) * 8;   // dst word offset
    uint4 wr[2];
    {   // tap 0 -> regs -> wt buffer 0 ; tap 1 -> regs
        const uint4* s4 = (const uint4*)wbase + tid * 2;
        wr[0] = s4[0]; wr[1] = s4[1];
        uint4* d = (uint4*)(sm + OFF_WT + wdo);
        d[0] = wr[0]; d[1] = wr[1];
        const uint4* s4b = (const uint4*)(wbase + 2048) + tid * 2;
        wr[0] = s4b[0]; wr[1] = s4b[1];
    }

    // ---- ldmatrix base addresses (byte, shared space) ----
    const uint32_t xs_sa = smem_u32(sm);
    const uint32_t wt_sa = xs_sa + OFF_WT * 4;
    const uint32_t A0 = xs_sa + ((warp * 34 + (lane & 15)) * XW) * 4 + (lane >> 4) * 16;
    const uint32_t B0 = wt_sa + (((lane & 7) + ((lane >> 4) & 1) * 8) * XW) * 4
                              + ((lane >> 3) & 1) * 16;

    __syncthreads();                                   // xs + wt0 ready

    float acc[2][8][4];
    #pragma unroll
    for (int mt = 0; mt < 2; ++mt)
        #pragma unroll
        for (int nt = 0; nt < 8; ++nt)
            #pragma unroll
            for (int j = 0; j < 4; ++j) acc[mt][nt][j] = 0.f;

    for (int j = 0; j < 9; ++j) {
        const int ky = j / 3, kx = j % 3, s = j & 1;
        const uint32_t Abase = A0 + (uint32_t)((ky * 34 + kx) * XW) * 4;
        const uint32_t Bbase = B0 + (uint32_t)(s * WTBUF) * 4;

        #pragma unroll
        for (int kt = 0; kt < 4; ++kt) {
            const uint32_t ko = (uint32_t)kt * 32;
            unsigned a[2][4], bq[4][4];
            ldsm_x4(a[0], Abase + ko);
            ldsm_x4(a[1], Abase + ko + 16 * XW * 4);
            #pragma unroll
            for (int q = 0; q < 4; ++q)
                ldsm_x4(bq[q], Bbase + ko + (uint32_t)(q * 16 * XW) * 4);
            #pragma unroll
            for (int mt = 0; mt < 2; ++mt) {
                #pragma unroll
                for (int q = 0; q < 4; ++q) {
                    mma_f16(acc[mt][2*q],   a[mt][0], a[mt][1], a[mt][2], a[mt][3],
                            bq[q][0], bq[q][1]);
                    mma_f16(acc[mt][2*q+1], a[mt][0], a[mt][1], a[mt][2], a[mt][3],
                            bq[q][2], bq[q][3]);
                }
            }
        }

        if (j < 8) {
            uint4* d = (uint4*)(sm + OFF_WT + (s ^ 1) * WTBUF + wdo);
            d[0] = wr[0]; d[1] = wr[1];
            if (j < 7) {
                const uint4* s4 = (const uint4*)(wbase + (size_t)(j+2)*2048) + tid*2;
                wr[0] = s4[0]; wr[1] = s4[1];
            }
        }
        __syncthreads();
    }

    // ---- epilogue: stage acc -> smem [ch][36] (conflict-free), coalesced I/O ----
    __syncthreads();                          // all LDSM reads of xs/wt done
    float* ss = (float*)sm + warp * 2304;     // 64 ch x 36 floats per warp
    const int gy = y0 + warp;
    float* ob = out + (size_t)b * 64 * PLANE;

    #pragma unroll
    for (int mt = 0; mt < 2; ++mt) {
        const int px = mt*16 + gq;
        #pragma unroll
        for (int nt = 0; nt < 8; ++nt) {
            const int c0 = nt*8 + 2*tq;
            ss[c0*36 + px]         = acc[mt][nt][0];
            ss[(c0+1)*36 + px]     = acc[mt][nt][1];
            ss[c0*36 + px + 8]     = acc[mt][nt][2];
            ss[(c0+1)*36 + px + 8] = acc[mt][nt][3];
        }
    }
    __syncwarp();
    const size_t gbase = (size_t)gy * WW + x0 + lane;
    #pragma unroll 8
    for (int c = 0; c < 64; ++c) {
        const size_t gi = (size_t)c * PLANE + gbase;
        ob[gi] = xb[gi] + ss[c*36 + lane];
    }
}

// ---------------------------------------------------------------------------
extern "C" void kernel_launch(void* const* d_in, const int* in_sizes, int n_in,
                              void* d_out, int out_size) {
    (void)in_sizes; (void)n_in; (void)out_size;
    const float* x     = (const float*)d_in[0];
    const float* vec   = (const float*)d_in[1];
    const float* gaff  = (const float*)d_in[2];
    const float* baff  = (const float*)d_in[3];
    const float* w1    = (const float*)d_in[4];
    const float* w2    = (const float*)d_in[5];
    const float* wconv = (const float*)d_in[6];
    float* out = (float*)d_out;

    mlp_kernel<<<NB, 256>>>(vec, w1, w2);
    dim3 dgrid(64, NB);
    demod_kernel<<<dgrid, 64>>>(wconv);

    const int smem = SMEM_WORDS * 4;
    cudaFuncSetAttribute(conv_kernel,
                         cudaFuncAttributeMaxDynamicSharedMemorySize, smem);
    dim3 grid(WW/32, HH/8, NB);
    conv_kernel<<<grid, 256, smem>>>(x, gaff, baff, out);
}